// round 13
// baseline (speedup 1.0000x reference)
#include <cuda_runtime.h>

// Problem shapes (fixed by the dataset problem)
#define BB 8
#define CC 64
#define HH 256
#define WW 256
#define HW (HH*WW)       // 65536

// Tile geometry: 32 wide x 16 tall, 1024 threads, 1 block/SM.
#define TTX 32
#define TTY 16
#define NT  1024
#define GXX (TTX+6)      // 38: gray region width  (halo 3)
#define GYY (TTY+6)      // 22: gray region height
#define DXX (TTX+2)      // 34: DoG region width   (halo 1)
#define DYY (TTY+2)      // 18: DoG region height
#define DN  (DXX*DYY)    // 612

// Gray float4 grid: span x0-4 .. x0+35 = 10 float4 per row (NJ), 22 rows.
#define NJ  10
#define NP  (GYY*NJ)     // 220 float4 positions
#define NG  8            // channel groups (8 channels each)
// Interior float4 positions: rows 3..18, cols j=1..8 -> 128 (= one per
// (position, ) with 8 channel-groups -> exactly 1024 interior tasks.

// ---------------------------------------------------------------------------
// Fully fused, register-staged:
//   Phase 1: each thread loads 8 float4 of x (its 8-channel slice of one
//            interior position) into REGISTERS, accumulates a channel-group
//            partial of gray; halo positions get float4 channel-group sums
//            too (discarded data). All partials meet in spart[220][8].
//   Phase 2/3: DoG(5x5, zero-pad) -> Sobel(3x3, zero-pad on DoG) -> att.
//   Phase 4: out = staged_regs * att, streaming stores. x is read from DRAM
//            exactly once and never re-read -- no L2-timing dependence.
// ---------------------------------------------------------------------------
__global__ void __launch_bounds__(NT, 1)
fused_kernel(const float* __restrict__ x,
             const float* __restrict__ gw,
             const float* __restrict__ gbv,
             float* __restrict__ out) {
    __shared__ __align__(16) float4 spart[NP][NG];     // 28 KB partial sums
    __shared__ float  sg[GYY][GXX + 2];                // gray region
    __shared__ float  sd[DYY][DXX + 2];                // dog region
    __shared__ __align__(16) float  sa[TTY][TTX];      // att (1 + sigmoid)
    __shared__ float  kd[25];                          // DoG weights

    const int tid = threadIdx.x;

    if (tid == 0) {
        // Normalized gaussian kernels exactly like the reference (fp32).
        float w1[25], w2[25];
        float s1 = 0.f, s2 = 0.f;
        #pragma unroll
        for (int i = 0; i < 25; ++i) {
            float dx = (float)(i / 5) - 2.0f;
            float dy = (float)(i % 5) - 2.0f;
            float r2 = dx * dx + dy * dy;
            float a = expf(-r2 * 0.5f);     // sigma = 1
            float b = expf(-r2 * 0.125f);   // sigma = 2
            w1[i] = a; w2[i] = b;
            s1 += a;  s2 += b;
        }
        float i1 = 1.0f / s1, i2 = 1.0f / s2;
        #pragma unroll
        for (int i = 0; i < 25; ++i) kd[i] = w1[i] * i1 - w2[i] * i2;
    }

    const int b  = blockIdx.z;
    const int x0 = blockIdx.x * TTX;
    const int y0 = blockIdx.y * TTY;
    const float* xb = x + (size_t)b * CC * HW;

    // ---- Phase 1a: interior — stage 8 float4 in regs, gray partial ----
    const int p   = tid & 127;          // interior float4 position 0..127
    const int g   = tid >> 7;           // channel group 0..7
    const int ir  = p >> 3;             // tile row 0..15
    const int ic4 = (p & 7) << 2;       // tile col 0,4,...,28
    const size_t ibase = (size_t)(g * 8) * HW + (size_t)(y0 + ir) * WW + (x0 + ic4);

    float4 stage[8];
    float4 acc;
    {
        #pragma unroll
        for (int i = 0; i < 8; ++i)
            stage[i] = __ldg((const float4*)(xb + ibase + (size_t)i * HW));
        float4 e0, e1;
        e0.x = stage[0].x + stage[1].x; e0.y = stage[0].y + stage[1].y;
        e0.z = stage[0].z + stage[1].z; e0.w = stage[0].w + stage[1].w;
        e1.x = stage[2].x + stage[3].x; e1.y = stage[2].y + stage[3].y;
        e1.z = stage[2].z + stage[3].z; e1.w = stage[2].w + stage[3].w;
        #pragma unroll
        for (int i = 4; i < 8; i += 2) {
            e0.x += stage[i].x;   e0.y += stage[i].y;
            e0.z += stage[i].z;   e0.w += stage[i].w;
            e1.x += stage[i+1].x; e1.y += stage[i+1].y;
            e1.z += stage[i+1].z; e1.w += stage[i+1].w;
        }
        acc.x = e0.x + e1.x; acc.y = e0.y + e1.y;
        acc.z = e0.z + e1.z; acc.w = e0.w + e1.w;
    }
    {
        // interior position -> gray grid pos: row 3+ir, col j = 1 + (p&7)
        int pos = (3 + ir) * NJ + 1 + (p & 7);
        spart[pos][g] = acc;
    }

    // ---- Phase 1b: halo — channel-group float4 sums (data discarded) ----
    for (int t = tid; t < NP * NG; t += NT) {
        int pos = t >> 3;
        int r = pos / NJ, j = pos - r * NJ;
        if (r >= 3 && r <= 18 && j >= 1 && j <= 8) continue;   // interior done
        int hg = t & 7;
        int gy = y0 - 3 + r;
        int gx4 = x0 - 4 + 4 * j;
        float4 hacc = make_float4(0.f, 0.f, 0.f, 0.f);
        if ((unsigned)gy < HH && gx4 >= 0 && gx4 + 3 < WW) {
            const float* hp = xb + (size_t)(hg * 8) * HW + (size_t)gy * WW + gx4;
            #pragma unroll
            for (int i = 0; i < 8; ++i) {
                float4 v = __ldg((const float4*)(hp + (size_t)i * HW));
                hacc.x += v.x; hacc.y += v.y; hacc.z += v.z; hacc.w += v.w;
            }
        }
        spart[pos][hg] = hacc;
    }
    __syncthreads();

    // ---- Phase 1c: reduce 8 groups -> gray, scatter to sg ----
    if (tid < NP) {
        float4 s0 = spart[tid][0], s1 = spart[tid][1];
        float4 s2 = spart[tid][2], s3 = spart[tid][3];
        float4 s4 = spart[tid][4], s5 = spart[tid][5];
        float4 s6 = spart[tid][6], s7 = spart[tid][7];
        const float sc = 1.0f / (float)CC;
        float g0 = (((s0.x + s1.x) + (s2.x + s3.x)) + ((s4.x + s5.x) + (s6.x + s7.x))) * sc;
        float g1 = (((s0.y + s1.y) + (s2.y + s3.y)) + ((s4.y + s5.y) + (s6.y + s7.y))) * sc;
        float g2 = (((s0.z + s1.z) + (s2.z + s3.z)) + ((s4.z + s5.z) + (s6.z + s7.z))) * sc;
        float g3 = (((s0.w + s1.w) + (s2.w + s3.w)) + ((s4.w + s5.w) + (s6.w + s7.w))) * sc;
        int r = tid / NJ, j = tid - r * NJ;
        int c0 = 4 * j - 1;                 // sg columns c0..c0+3
        if (c0 >= 0)        sg[r][c0    ] = g0;
                            sg[r][c0 + 1] = g1;
                            sg[r][c0 + 2] = g2;
        if (c0 + 3 < GXX)   sg[r][c0 + 3] = g3;
    }
    __syncthreads();

    // ---- Phase 2: DoG on tile + halo(1); out-of-image DoG forced to 0 ----
    for (int i = tid; i < DN; i += NT) {
        int r = i / DXX, c = i - r * DXX;
        int gy = y0 - 1 + r, gx = x0 - 1 + c;
        float vv = 0.f;
        if ((unsigned)gy < HH && (unsigned)gx < WW) {
            float a2 = 0.f;
            #pragma unroll
            for (int ki = 0; ki < 5; ++ki)
                #pragma unroll
                for (int kj = 0; kj < 5; ++kj)
                    a2 += kd[ki * 5 + kj] * sg[r + ki][c + kj];
            vv = a2;
        }
        sd[r][c] = vv;
    }
    __syncthreads();

    // ---- Phase 3: Sobel -> magnitude -> sigmoid gate ----
    if (tid < TTY * TTX) {
        const int py = tid >> 5;       // 0..15
        const int px = tid & 31;       // 0..31
        float d00 = sd[py    ][px    ], d01 = sd[py    ][px + 1], d02 = sd[py    ][px + 2];
        float d10 = sd[py + 1][px    ],                            d12 = sd[py + 1][px + 2];
        float d20 = sd[py + 2][px    ], d21 = sd[py + 2][px + 1], d22 = sd[py + 2][px + 2];
        float gxv = (d02 - d00) + 2.0f * (d12 - d10) + (d22 - d20);
        float gyv = (d20 - d00) + 2.0f * (d21 - d01) + (d22 - d02);
        float mag = sqrtf(gxv * gxv + gyv * gyv + 1e-6f);
        float tv  = mag * gw[0] + gbv[0];
        sa[py][px] = 1.0f + 1.0f / (1.0f + expf(-tv));
    }
    __syncthreads();

    // ---- Phase 4: out = staged regs * att, streaming stores ----
    {
        float4 a = *(const float4*)&sa[ir][ic4];
        float* po = out + (size_t)b * CC * HW + ibase;
        #pragma unroll
        for (int i = 0; i < 8; ++i) {
            float4 v = stage[i];
            v.x *= a.x; v.y *= a.y; v.z *= a.z; v.w *= a.w;
            __stcs((float4*)(po + (size_t)i * HW), v);
        }
    }
}

// ---------------------------------------------------------------------------
extern "C" void kernel_launch(void* const* d_in, const int* in_sizes, int n_in,
                              void* d_out, int out_size) {
    const float* x  = (const float*)d_in[0];
    const float* gw = (const float*)d_in[1];
    const float* gb = (const float*)d_in[2];
    float* out = (float*)d_out;

    dim3 grid(WW / TTX, HH / TTY, BB);   // 8 x 16 x 8 = 1024 blocks
    fused_kernel<<<grid, NT>>>(x, gw, gb, out);
}

// round 14
// speedup vs baseline: 1.0837x; 1.0837x over previous
#include <cuda_runtime.h>

// Problem shapes (fixed by the dataset problem)
#define BB 8
#define CC 64
#define HH 256
#define WW 256
#define HW (HH*WW)       // 65536

// Tile geometry: 32 wide x 16 tall, 512 threads, 2 blocks/SM.
#define TTX 32
#define TTY 16
#define NT  512
#define GXX (TTX+6)      // 38: gray region width  (halo 3)
#define GYY (TTY+6)      // 22: gray region height
#define DXX (TTX+2)      // 34: DoG region width   (halo 1)
#define DYY (TTY+2)      // 18: DoG region height
#define DN  (DXX*DYY)    // 612

// Gray float4 grid: span x0-4 .. x0+35 = 10 float4 per row (NJ), 22 rows.
#define NJ  10
#define NP  (GYY*NJ)     // 220 float4 positions
#define NG  4            // 4 channel groups; each = 8 staged + 8 summed ch

// ---------------------------------------------------------------------------
// Half-register-staged fused kernel, 2 barrier domains per SM:
//   Phase 1: thread (p, g) loads its interior position's channels
//            [8g, 8g+8) into REGISTERS (kept to phase 4) and channels
//            [32+8g, 32+8g+8) sum-only; partial gray -> spart[pos][g].
//            Halo positions (92) summed float4-wise (L2 hits from neighbors).
//   Phase 2/3: DoG(5x5, zero-pad) -> Sobel(3x3, zero-pad on DoG) -> att.
//   Phase 4: staged half multiplied from regs (no re-read); high half
//            re-read (64 KB/tile working set -> guaranteed L2 hit), both
//            stored with __stcs.
// 2 blocks/SM phase-offset so one block streams memory while the other
// sits in barriers/compute (fixes R13's single-domain serialization).
// ---------------------------------------------------------------------------
__global__ void __launch_bounds__(NT, 2)
fused_kernel(const float* __restrict__ x,
             const float* __restrict__ gw,
             const float* __restrict__ gbv,
             float* __restrict__ out) {
    __shared__ __align__(16) float4 spart[NP][NG];   // 14 KB partial sums
    __shared__ float  sg[GYY][GXX + 2];              // gray region
    __shared__ float  sd[DYY][DXX + 2];              // dog region
    __shared__ __align__(16) float sa[TTY][TTX];     // att (1 + sigmoid)
    __shared__ float  kd[25];                        // DoG weights

    const int tid = threadIdx.x;

    if (tid == 0) {
        // Normalized gaussian kernels exactly like the reference (fp32).
        float w1[25], w2[25];
        float s1 = 0.f, s2 = 0.f;
        #pragma unroll
        for (int i = 0; i < 25; ++i) {
            float dx = (float)(i / 5) - 2.0f;
            float dy = (float)(i % 5) - 2.0f;
            float r2 = dx * dx + dy * dy;
            float a = expf(-r2 * 0.5f);     // sigma = 1
            float b = expf(-r2 * 0.125f);   // sigma = 2
            w1[i] = a; w2[i] = b;
            s1 += a;  s2 += b;
        }
        float i1 = 1.0f / s1, i2 = 1.0f / s2;
        #pragma unroll
        for (int i = 0; i < 25; ++i) kd[i] = w1[i] * i1 - w2[i] * i2;
    }

    const int b  = blockIdx.z;
    const int x0 = blockIdx.x * TTX;
    const int y0 = blockIdx.y * TTY;
    const float* xb = x + (size_t)b * CC * HW;

    // ---- Phase 1a: interior — stage low half, sum both halves ----
    const int p   = tid & 127;          // interior float4 position 0..127
    const int g   = tid >> 7;           // channel group 0..3
    const int ir  = p >> 3;             // tile row 0..15
    const int ic4 = (p & 7) << 2;       // tile col 0,4,...,28
    const size_t posoff = (size_t)(y0 + ir) * WW + (x0 + ic4);
    const float* plo = xb + (size_t)(g * 8) * HW + posoff;        // staged
    const float* phi = plo + (size_t)32 * HW;                     // sum-only

    float4 stage[8];
    float4 acc;
    {
        float4 e0 = make_float4(0.f,0.f,0.f,0.f);
        float4 e1 = make_float4(0.f,0.f,0.f,0.f);
        #pragma unroll
        for (int i = 0; i < 8; i += 2) {
            stage[i]     = __ldg((const float4*)(plo + (size_t)i * HW));
            stage[i + 1] = __ldg((const float4*)(plo + (size_t)(i + 1) * HW));
            e0.x += stage[i].x;   e0.y += stage[i].y;
            e0.z += stage[i].z;   e0.w += stage[i].w;
            e1.x += stage[i+1].x; e1.y += stage[i+1].y;
            e1.z += stage[i+1].z; e1.w += stage[i+1].w;
        }
        #pragma unroll
        for (int i = 0; i < 8; i += 2) {
            float4 v0 = __ldg((const float4*)(phi + (size_t)i * HW));
            float4 v1 = __ldg((const float4*)(phi + (size_t)(i + 1) * HW));
            e0.x += v0.x; e0.y += v0.y; e0.z += v0.z; e0.w += v0.w;
            e1.x += v1.x; e1.y += v1.y; e1.z += v1.z; e1.w += v1.w;
        }
        acc.x = e0.x + e1.x; acc.y = e0.y + e1.y;
        acc.z = e0.z + e1.z; acc.w = e0.w + e1.w;
    }
    spart[(3 + ir) * NJ + 1 + (p & 7)][g] = acc;

    // ---- Phase 1b: halo — 16-channel group sums (92 positions x 4) ----
    for (int t = tid; t < NP * NG; t += NT) {
        int pos = t >> 2;
        int r = pos / NJ, j = pos - r * NJ;
        if (r >= 3 && r < 3 + TTY && j >= 1 && j < 9) continue;   // interior
        int hg = t & 3;
        int gy = y0 - 3 + r;
        int gx4 = x0 - 4 + 4 * j;
        float4 hacc = make_float4(0.f, 0.f, 0.f, 0.f);
        if ((unsigned)gy < HH && gx4 >= 0 && gx4 + 3 < WW) {
            const float* hp = xb + (size_t)(hg * 8) * HW + (size_t)gy * WW + gx4;
            #pragma unroll
            for (int i = 0; i < 8; ++i) {
                float4 v = __ldg((const float4*)(hp + (size_t)i * HW));
                hacc.x += v.x; hacc.y += v.y; hacc.z += v.z; hacc.w += v.w;
            }
            const float* hp2 = hp + (size_t)32 * HW;
            #pragma unroll
            for (int i = 0; i < 8; ++i) {
                float4 v = __ldg((const float4*)(hp2 + (size_t)i * HW));
                hacc.x += v.x; hacc.y += v.y; hacc.z += v.z; hacc.w += v.w;
            }
        }
        spart[pos][hg] = hacc;
    }
    __syncthreads();

    // ---- Phase 1c: reduce 4 groups -> gray, scatter to sg ----
    if (tid < NP) {
        float4 s0 = spart[tid][0], s1 = spart[tid][1];
        float4 s2 = spart[tid][2], s3 = spart[tid][3];
        const float sc = 1.0f / (float)CC;
        float g0 = ((s0.x + s1.x) + (s2.x + s3.x)) * sc;
        float g1 = ((s0.y + s1.y) + (s2.y + s3.y)) * sc;
        float g2 = ((s0.z + s1.z) + (s2.z + s3.z)) * sc;
        float g3 = ((s0.w + s1.w) + (s2.w + s3.w)) * sc;
        int r = tid / NJ, j = tid - r * NJ;
        int c0 = 4 * j - 1;                 // sg columns c0..c0+3
        if (c0 >= 0)        sg[r][c0    ] = g0;
                            sg[r][c0 + 1] = g1;
                            sg[r][c0 + 2] = g2;
        if (c0 + 3 < GXX)   sg[r][c0 + 3] = g3;
    }
    __syncthreads();

    // ---- Phase 2: DoG on tile + halo(1); out-of-image DoG forced to 0 ----
    for (int i = tid; i < DN; i += NT) {
        int r = i / DXX, c = i - r * DXX;
        int gy = y0 - 1 + r, gx = x0 - 1 + c;
        float vv = 0.f;
        if ((unsigned)gy < HH && (unsigned)gx < WW) {
            float a2 = 0.f;
            #pragma unroll
            for (int ki = 0; ki < 5; ++ki)
                #pragma unroll
                for (int kj = 0; kj < 5; ++kj)
                    a2 += kd[ki * 5 + kj] * sg[r + ki][c + kj];
            vv = a2;
        }
        sd[r][c] = vv;
    }
    __syncthreads();

    // ---- Phase 3: Sobel -> magnitude -> sigmoid gate (one pixel/thread) ----
    {
        const int py = tid >> 5;       // 0..15
        const int px = tid & 31;       // 0..31
        float d00 = sd[py    ][px    ], d01 = sd[py    ][px + 1], d02 = sd[py    ][px + 2];
        float d10 = sd[py + 1][px    ],                            d12 = sd[py + 1][px + 2];
        float d20 = sd[py + 2][px    ], d21 = sd[py + 2][px + 1], d22 = sd[py + 2][px + 2];
        float gxv = (d02 - d00) + 2.0f * (d12 - d10) + (d22 - d20);
        float gyv = (d20 - d00) + 2.0f * (d21 - d01) + (d22 - d02);
        float mag = sqrtf(gxv * gxv + gyv * gyv + 1e-6f);
        float tv  = mag * gw[0] + gbv[0];
        sa[py][px] = 1.0f + 1.0f / (1.0f + expf(-tv));
    }
    __syncthreads();

    // ---- Phase 4: staged half from regs; high half re-read (L2 hit) ----
    {
        float4 a = *(const float4*)&sa[ir][ic4];
        float* po  = out + (size_t)b * CC * HW + (size_t)(g * 8) * HW + posoff;
        float* po2 = po + (size_t)32 * HW;
        #pragma unroll
        for (int i = 0; i < 8; ++i) {
            float4 v = stage[i];
            v.x *= a.x; v.y *= a.y; v.z *= a.z; v.w *= a.w;
            __stcs((float4*)(po + (size_t)i * HW), v);
        }
        #pragma unroll
        for (int i = 0; i < 8; ++i) {
            float4 v = __ldg((const float4*)(phi + (size_t)i * HW));
            v.x *= a.x; v.y *= a.y; v.z *= a.z; v.w *= a.w;
            __stcs((float4*)(po2 + (size_t)i * HW), v);
        }
    }
}

// ---------------------------------------------------------------------------
extern "C" void kernel_launch(void* const* d_in, const int* in_sizes, int n_in,
                              void* d_out, int out_size) {
    const float* x  = (const float*)d_in[0];
    const float* gw = (const float*)d_in[1];
    const float* gb = (const float*)d_in[2];
    float* out = (float*)d_out;

    dim3 grid(WW / TTX, HH / TTY, BB);   // 8 x 16 x 8 = 1024 blocks
    fused_kernel<<<grid, NT>>>(x, gw, gb, out);
}

// round 15
// speedup vs baseline: 1.2114x; 1.1178x over previous
#include <cuda_runtime.h>

// Problem shapes (fixed by the dataset problem)
#define BB 8
#define CC 64
#define HH 256
#define WW 256
#define HW (HH*WW)       // 65536

// Tile geometry: 32 wide x 16 tall, 512 threads, 3 blocks/SM.
#define TTX 32
#define TTY 16
#define NT  512
#define GXX (TTX+6)      // 38: gray region width  (halo 3)
#define GYY (TTY+6)      // 22: gray region height
#define DXX (TTX+2)      // 34: DoG region width   (halo 1)
#define DYY (TTY+2)      // 18: DoG region height
#define DN  (DXX*DYY)    // 612

// Gray phase float4 layout: span x0-4 .. x0+35 = 10 float4 per row, 22 rows.
#define NJ  10
#define NP  (GYY*NJ)     // 220 float4 positions
#define NTASK (NP*2)     // 440 = 2-way channel split

// ---------------------------------------------------------------------------
// Fully fused (R10 structure = best known):
//   gray = mean_c(x) over tile+halo(3)   [x read #1: float4, DRAM first-touch]
//   -> DoG(5x5, zero-pad) -> Sobel(3x3, zero-pad on DoG) -> att in smem
//   -> out = x * (1 + att)               [x read #2: float4 __ldcs (last use,
//                                         evict-first) -> frees L2 for other
//                                         tiles' pending re-reads; __stcs
//                                         stores keep the write stream out
//                                         of L2's useful capacity]
// 3 blocks/SM: co-resident footprint ~114 MB just fits L2 (the knee of the
// bytes-vs-BW tradeoff measured across R7/R10/R12).
// ---------------------------------------------------------------------------
__global__ void __launch_bounds__(NT, 3)
fused_kernel(const float* __restrict__ x,
             const float* __restrict__ gw,
             const float* __restrict__ gbv,
             float* __restrict__ out) {
    __shared__ float  sg[GYY][GXX + 2];  // gray region (padded cols)
    __shared__ float4 spart[NP];         // channel-half partial sums
    __shared__ float  sd[DYY][DXX + 2];  // dog region
    __shared__ __align__(16) float sa[TTY][TTX];  // att (1 + sigmoid)
    __shared__ float  kd[25];            // DoG weights (gk1 - gk2)

    const int tid = threadIdx.x;

    if (tid == 0) {
        // Normalized gaussian kernels exactly like the reference (fp32).
        float w1[25], w2[25];
        float s1 = 0.f, s2 = 0.f;
        #pragma unroll
        for (int i = 0; i < 25; ++i) {
            float dx = (float)(i / 5) - 2.0f;
            float dy = (float)(i % 5) - 2.0f;
            float r2 = dx * dx + dy * dy;
            float a = expf(-r2 * 0.5f);     // sigma = 1
            float b = expf(-r2 * 0.125f);   // sigma = 2
            w1[i] = a; w2[i] = b;
            s1 += a;  s2 += b;
        }
        float i1 = 1.0f / s1, i2 = 1.0f / s2;
        #pragma unroll
        for (int i = 0; i < 25; ++i) kd[i] = w1[i] * i1 - w2[i] * i2;
    }

    const int b  = blockIdx.z;
    const int x0 = blockIdx.x * TTX;
    const int y0 = blockIdx.y * TTY;
    const float* xb = x + (size_t)b * CC * HW;

    // ---- Phase 1a: float4 gray partial sums (2-way channel split) ----
    float4 acc = make_float4(0.f, 0.f, 0.f, 0.f);
    int pos = -1, half = 0;
    if (tid < NTASK) {
        half = (tid >= NP);
        pos  = tid - (half ? NP : 0);
        int r  = pos / NJ;
        int j  = pos - r * NJ;
        int gy = y0 - 3 + r;
        int gx4 = x0 - 4 + 4 * j;
        if ((unsigned)gy < HH && gx4 >= 0 && gx4 + 3 < WW) {
            const float4* p = (const float4*)(xb + (size_t)gy * WW + gx4)
                            + (size_t)half * 32 * (HW / 4);
            float4 a0 = make_float4(0.f,0.f,0.f,0.f);
            float4 a1 = make_float4(0.f,0.f,0.f,0.f);
            float4 a2 = make_float4(0.f,0.f,0.f,0.f);
            float4 a3 = make_float4(0.f,0.f,0.f,0.f);
            #pragma unroll
            for (int cc = 0; cc < 32; cc += 4) {
                float4 v0 = __ldg(p + (size_t)(cc + 0) * (HW / 4));
                float4 v1 = __ldg(p + (size_t)(cc + 1) * (HW / 4));
                float4 v2 = __ldg(p + (size_t)(cc + 2) * (HW / 4));
                float4 v3 = __ldg(p + (size_t)(cc + 3) * (HW / 4));
                a0.x += v0.x; a0.y += v0.y; a0.z += v0.z; a0.w += v0.w;
                a1.x += v1.x; a1.y += v1.y; a1.z += v1.z; a1.w += v1.w;
                a2.x += v2.x; a2.y += v2.y; a2.z += v2.z; a2.w += v2.w;
                a3.x += v3.x; a3.y += v3.y; a3.z += v3.z; a3.w += v3.w;
            }
            acc.x = (a0.x + a1.x) + (a2.x + a3.x);
            acc.y = (a0.y + a1.y) + (a2.y + a3.y);
            acc.z = (a0.z + a1.z) + (a2.z + a3.z);
            acc.w = (a0.w + a1.w) + (a2.w + a3.w);
        }
        if (half) spart[pos] = acc;
    }
    __syncthreads();

    // ---- Phase 1b: combine halves, scatter into sg (drop c=-1 and c=38) ----
    if (tid < NP && !half) {
        float4 o = spart[pos];
        const float sc = 1.0f / (float)CC;
        float g0 = (o.x + acc.x) * sc;
        float g1 = (o.y + acc.y) * sc;
        float g2 = (o.z + acc.z) * sc;
        float g3 = (o.w + acc.w) * sc;
        int r = pos / NJ;
        int j = pos - r * NJ;
        int c0 = 4 * j - 1;                 // sg columns c0..c0+3
        if (c0 >= 0)        sg[r][c0    ] = g0;
                            sg[r][c0 + 1] = g1;
                            sg[r][c0 + 2] = g2;
        if (c0 + 3 < GXX)   sg[r][c0 + 3] = g3;
    }
    __syncthreads();

    // ---- Phase 2: DoG on tile + halo(1); out-of-image DoG forced to 0 ----
    for (int i = tid; i < DN; i += NT) {
        int r = i / DXX, c = i - r * DXX;
        int gy = y0 - 1 + r, gx = x0 - 1 + c;
        float vv = 0.f;
        if ((unsigned)gy < HH && (unsigned)gx < WW) {
            float a2 = 0.f;
            #pragma unroll
            for (int ki = 0; ki < 5; ++ki)
                #pragma unroll
                for (int kj = 0; kj < 5; ++kj)
                    a2 += kd[ki * 5 + kj] * sg[r + ki][c + kj];
            vv = a2;
        }
        sd[r][c] = vv;
    }
    __syncthreads();

    // ---- Phase 3: Sobel -> magnitude -> sigmoid gate (one pixel/thread) ----
    {
        const int py = tid >> 5;       // 0..15
        const int px = tid & 31;       // 0..31
        float d00 = sd[py    ][px    ], d01 = sd[py    ][px + 1], d02 = sd[py    ][px + 2];
        float d10 = sd[py + 1][px    ],                            d12 = sd[py + 1][px + 2];
        float d20 = sd[py + 2][px    ], d21 = sd[py + 2][px + 1], d22 = sd[py + 2][px + 2];
        float gxv = (d02 - d00) + 2.0f * (d12 - d10) + (d22 - d20);
        float gyv = (d20 - d00) + 2.0f * (d21 - d01) + (d22 - d02);
        float mag = sqrtf(gxv * gxv + gyv * gyv + 1e-6f);
        float tv  = mag * gw[0] + gbv[0];
        sa[py][px] = 1.0f + 1.0f / (1.0f + expf(-tv));
    }
    __syncthreads();

    // ---- Phase 4: out = x * att; __ldcs re-read (last use), __stcs store ----
    // Tile per channel = 16 rows x 8 float4; 8192 float4 total, 16 per thread.
    #pragma unroll 4
    for (int f = tid; f < (TTY * TTX / 4) * CC; f += NT) {
        int c  = f >> 7;               // channel
        int q  = f & 127;              // float4 slot within tile
        int r  = q >> 3;               // row 0..15
        int c4 = (q & 7) << 2;         // col 0,4,...,28
        size_t off = (size_t)c * HW + (size_t)(y0 + r) * WW + (x0 + c4);
        float4 v = __ldcs((const float4*)(xb + off));
        float4 a = *(const float4*)&sa[r][c4];
        v.x *= a.x; v.y *= a.y; v.z *= a.z; v.w *= a.w;
        __stcs((float4*)(out + (size_t)b * CC * HW + off), v);
    }
}

// ---------------------------------------------------------------------------
extern "C" void kernel_launch(void* const* d_in, const int* in_sizes, int n_in,
                              void* d_out, int out_size) {
    const float* x  = (const float*)d_in[0];
    const float* gw = (const float*)d_in[1];
    const float* gb = (const float*)d_in[2];
    float* out = (float*)d_out;

    dim3 grid(WW / TTX, HH / TTY, BB);   // 8 x 16 x 8 = 1024 blocks
    fused_kernel<<<grid, NT>>>(x, gw, gb, out);
}

// round 17
// speedup vs baseline: 1.2578x; 1.0383x over previous
#include <cuda_runtime.h>

// Problem shapes (fixed by the dataset problem)
#define BB 8
#define CC 64
#define HH 256
#define WW 256
#define HW (HH*WW)       // 65536

// Tile geometry: 32 wide x 16 tall, 512 threads, 3 blocks/SM.
#define TTX 32
#define TTY 16
#define NT  512
#define GXX (TTX+6)      // 38: gray region width  (halo 3)
#define GYY (TTY+6)      // 22: gray region height
#define DXX (TTX+2)      // 34: DoG region width   (halo 1)
#define DYY (TTY+2)      // 18: DoG region height
#define DN  (DXX*DYY)    // 612

// Gray phase float4 layout: span x0-4 .. x0+35 = 10 float4 per row, 22 rows.
#define NJ  10
#define NP  (GYY*NJ)     // 220 float4 positions
#define NTASK (NP*2)     // 440 = 2-way channel split

// ---------------------------------------------------------------------------
// Fully fused (R10 structure = best known), with the phase-3->4 barrier
// REMOVED: each thread computes the 4 att values its phase-4 iterations
// consume (its q-slot is constant across all 16 channel steps) directly
// from sd, so warps flow from Sobel/sigmoid straight into phase-4 memory
// streaming without waiting for the whole block. This spreads phase-4 load
// issue across the phase boundary (the profile shows a serialization-
// limited kernel: DRAM 47%, L1 49%, issue 18% -- nothing saturated).
// ---------------------------------------------------------------------------
__global__ void __launch_bounds__(NT, 3)
fused_kernel(const float* __restrict__ x,
             const float* __restrict__ gw,
             const float* __restrict__ gbv,
             float* __restrict__ out) {
    __shared__ float  sg[GYY][GXX + 2];  // gray region (padded cols)
    __shared__ float4 spart[NP];         // channel-half partial sums
    __shared__ float  sd[DYY][DXX + 2];  // dog region
    __shared__ float  kd[25];            // DoG weights (gk1 - gk2)

    const int tid = threadIdx.x;

    if (tid == 0) {
        // Normalized gaussian kernels exactly like the reference (fp32).
        float w1[25], w2[25];
        float s1 = 0.f, s2 = 0.f;
        #pragma unroll
        for (int i = 0; i < 25; ++i) {
            float dx = (float)(i / 5) - 2.0f;
            float dy = (float)(i % 5) - 2.0f;
            float r2 = dx * dx + dy * dy;
            float a = expf(-r2 * 0.5f);     // sigma = 1
            float b = expf(-r2 * 0.125f);   // sigma = 2
            w1[i] = a; w2[i] = b;
            s1 += a;  s2 += b;
        }
        float i1 = 1.0f / s1, i2 = 1.0f / s2;
        #pragma unroll
        for (int i = 0; i < 25; ++i) kd[i] = w1[i] * i1 - w2[i] * i2;
    }

    const int b  = blockIdx.z;
    const int x0 = blockIdx.x * TTX;
    const int y0 = blockIdx.y * TTY;
    const float* xb = x + (size_t)b * CC * HW;

    // ---- Phase 1a: float4 gray partial sums (2-way channel split) ----
    float4 acc = make_float4(0.f, 0.f, 0.f, 0.f);
    int pos = -1, half = 0;
    if (tid < NTASK) {
        half = (tid >= NP);
        pos  = tid - (half ? NP : 0);
        int r  = pos / NJ;
        int j  = pos - r * NJ;
        int gy = y0 - 3 + r;
        int gx4 = x0 - 4 + 4 * j;
        if ((unsigned)gy < HH && gx4 >= 0 && gx4 + 3 < WW) {
            const float4* p = (const float4*)(xb + (size_t)gy * WW + gx4)
                            + (size_t)half * 32 * (HW / 4);
            float4 a0 = make_float4(0.f,0.f,0.f,0.f);
            float4 a1 = make_float4(0.f,0.f,0.f,0.f);
            float4 a2 = make_float4(0.f,0.f,0.f,0.f);
            float4 a3 = make_float4(0.f,0.f,0.f,0.f);
            #pragma unroll
            for (int cc = 0; cc < 32; cc += 4) {
                float4 v0 = __ldg(p + (size_t)(cc + 0) * (HW / 4));
                float4 v1 = __ldg(p + (size_t)(cc + 1) * (HW / 4));
                float4 v2 = __ldg(p + (size_t)(cc + 2) * (HW / 4));
                float4 v3 = __ldg(p + (size_t)(cc + 3) * (HW / 4));
                a0.x += v0.x; a0.y += v0.y; a0.z += v0.z; a0.w += v0.w;
                a1.x += v1.x; a1.y += v1.y; a1.z += v1.z; a1.w += v1.w;
                a2.x += v2.x; a2.y += v2.y; a2.z += v2.z; a2.w += v2.w;
                a3.x += v3.x; a3.y += v3.y; a3.z += v3.z; a3.w += v3.w;
            }
            acc.x = (a0.x + a1.x) + (a2.x + a3.x);
            acc.y = (a0.y + a1.y) + (a2.y + a3.y);
            acc.z = (a0.z + a1.z) + (a2.z + a3.z);
            acc.w = (a0.w + a1.w) + (a2.w + a3.w);
        }
        if (half) spart[pos] = acc;
    }
    __syncthreads();

    // ---- Phase 1b: combine halves, scatter into sg (drop c=-1 and c=38) ----
    if (tid < NP && !half) {
        float4 o = spart[pos];
        const float sc = 1.0f / (float)CC;
        float g0 = (o.x + acc.x) * sc;
        float g1 = (o.y + acc.y) * sc;
        float g2 = (o.z + acc.z) * sc;
        float g3 = (o.w + acc.w) * sc;
        int r = pos / NJ;
        int j = pos - r * NJ;
        int c0 = 4 * j - 1;                 // sg columns c0..c0+3
        if (c0 >= 0)        sg[r][c0    ] = g0;
                            sg[r][c0 + 1] = g1;
                            sg[r][c0 + 2] = g2;
        if (c0 + 3 < GXX)   sg[r][c0 + 3] = g3;
    }
    __syncthreads();

    // ---- Phase 2: DoG on tile + halo(1); out-of-image DoG forced to 0 ----
    for (int i = tid; i < DN; i += NT) {
        int r = i / DXX, c = i - r * DXX;
        int gy = y0 - 1 + r, gx = x0 - 1 + c;
        float vv = 0.f;
        if ((unsigned)gy < HH && (unsigned)gx < WW) {
            float a2 = 0.f;
            #pragma unroll
            for (int ki = 0; ki < 5; ++ki)
                #pragma unroll
                for (int kj = 0; kj < 5; ++kj)
                    a2 += kd[ki * 5 + kj] * sg[r + ki][c + kj];
            vv = a2;
        }
        sd[r][c] = vv;
    }
    __syncthreads();

    // ---- Phase 3+4 merged (no barrier between them): each thread computes
    //      the att float4 for its own phase-4 q-slot, then streams channels.
    const int q  = tid & 127;          // float4 slot, constant across c-steps
    const int r  = q >> 3;             // row 0..15
    const int c4 = (q & 7) << 2;       // col 0,4,...,28
    const float gwv = gw[0], gbvv = gbv[0];

    float att[4];
    #pragma unroll
    for (int k = 0; k < 4; ++k) {
        int px = c4 + k;
        float d00 = sd[r    ][px    ], d01 = sd[r    ][px + 1], d02 = sd[r    ][px + 2];
        float d10 = sd[r + 1][px    ],                           d12 = sd[r + 1][px + 2];
        float d20 = sd[r + 2][px    ], d21 = sd[r + 2][px + 1], d22 = sd[r + 2][px + 2];
        float gxv = (d02 - d00) + 2.0f * (d12 - d10) + (d22 - d20);
        float gyv = (d20 - d00) + 2.0f * (d21 - d01) + (d22 - d02);
        float mag = sqrtf(gxv * gxv + gyv * gyv + 1e-6f);
        float tv  = mag * gwv + gbvv;
        att[k] = 1.0f + 1.0f / (1.0f + expf(-tv));
    }
    float4 a = make_float4(att[0], att[1], att[2], att[3]);

    // Phase 4: 16 channel steps; c = (tid>>7) + 4k. x re-read hits L2.
    const size_t poff = (size_t)(y0 + r) * WW + (x0 + c4);
    const int   cbase = tid >> 7;            // 0..3
    float* ob = out + (size_t)b * CC * HW;
    #pragma unroll 4
    for (int k = 0; k < 16; ++k) {
        int c = cbase + (k << 2);
        size_t off = (size_t)c * HW + poff;
        float4 v = __ldg((const float4*)(xb + off));
        v.x *= a.x; v.y *= a.y; v.z *= a.z; v.w *= a.w;
        __stcs((float4*)(ob + off), v);
    }
}

// ---------------------------------------------------------------------------
extern "C" void kernel_launch(void* const* d_in, const int* in_sizes, int n_in,
                              void* d_out, int out_size) {
    const float* x  = (const float*)d_in[0];
    const float* gw = (const float*)d_in[1];
    const float* gb = (const float*)d_in[2];
    float* out = (float*)d_out;

    dim3 grid(WW / TTX, HH / TTY, BB);   // 8 x 16 x 8 = 1024 blocks
    fused_kernel<<<grid, NT>>>(x, gw, gb, out);
}